// round 1
// baseline (speedup 1.0000x reference)
#include <cuda_runtime.h>
#include <cuda_bf16.h>
#include <mma.h>

using namespace nvcuda;

// ---------------------------------------------------------------------------
// Problem constants
//   B=8, NK=NQ=2048, D=256, H=1024
//   Wk = KEY  @ Wk_w.T + Wk_b   [8,2048,1024]
//   Wq = QUERY@ Wq_w.T + Wq_b   [8,2048,1024]
//   Wv = VALUE@ Wv_w.T + Wv_b   [8,2048,1024]
//   dist[b,i,k] = sum_h Wk[b,i,h]*Wq[b,k,h] / 32        [8,2048,2048]
//   weights = softmax(dist, axis=k)  (row-wise, contiguous)
//   ctx[b,k,h] = sum_i weights[b,i,k]*Wv[b,i,h]          [8,2048,1024]
//   out = ctx @ lin_w.T + lin_b                          [8,2048,256]
// ---------------------------------------------------------------------------

#define BM 128
#define BN 128
#define BK 32
#define NTHREADS 256

// Scratch (device globals: allocation is forbidden)
__device__ float g_Wk[16777216];    // 8*2048*1024
__device__ float g_Wq[16777216];
__device__ float g_Wv[16777216];
__device__ float g_dist[33554432];  // 8*2048*2048
__device__ float g_ctx[16777216];

__device__ __forceinline__ float to_tf32(float x) {
    float r;
    asm("cvt.rna.tf32.f32 %0, %1;" : "=f"(r) : "f"(x));
    return r;
}

// Generic TF32 WMMA GEMM:  C[m,n] = alpha * sum_k A[m,k]*B[k,n] (+ bias[n])
// A_COL:  A element (m,k) at  A[k*lda + m]   (else A[m*lda + k])
// B_ROW:  B element (k,n) at  B[k*ldb + n]   (else B[n*ldb + k])
// Batched via blockIdx.z with 64-bit strides.
template<bool A_COL, bool B_ROW>
__global__ void __launch_bounds__(NTHREADS)
gemm_tf32(const float* __restrict__ A, const float* __restrict__ B,
          float* __restrict__ C, const float* __restrict__ bias,
          int M, int N, int K, int lda, int ldb, int ldc,
          long long strideA, long long strideB, long long strideC,
          float alpha)
{
    __shared__ float As[BM][BK + 8];
    __shared__ float Bs[BK][BN + 8];
    __shared__ float stage[8][16][20];

    const float* Ab = A + (long long)blockIdx.z * strideA;
    const float* Bb = B + (long long)blockIdx.z * strideB;
    float*       Cb = C + (long long)blockIdx.z * strideC;

    const int m0 = blockIdx.y * BM;
    const int n0 = blockIdx.x * BN;
    const int tid = threadIdx.x;

    const int wid  = tid >> 5;
    const int lane = tid & 31;
    const int wm = (wid >> 2) * 64;   // warp row offset (2 rows of warps)
    const int wn = (wid & 3) * 32;    // warp col offset (4 cols of warps)

    using FragA = wmma::fragment<wmma::matrix_a, 16, 16, 8, wmma::precision::tf32, wmma::row_major>;
    using FragB = wmma::fragment<wmma::matrix_b, 16, 16, 8, wmma::precision::tf32, wmma::row_major>;
    using FragC = wmma::fragment<wmma::accumulator, 16, 16, 8, float>;

    FragC cf[4][2];
#pragma unroll
    for (int i = 0; i < 4; i++)
#pragma unroll
        for (int j = 0; j < 2; j++)
            wmma::fill_fragment(cf[i][j], 0.0f);

    for (int k0 = 0; k0 < K; k0 += BK) {
        // ---- load A tile -> As[m][k] (tf32-rounded) ----
        if (!A_COL) {
#pragma unroll
            for (int r = 0; r < 4; r++) {
                int idx = tid + NTHREADS * r;       // 0..1023
                int row = idx >> 3;                 // 0..127
                int c4  = (idx & 7) * 4;            // 0..28
                float4 v = *(const float4*)(Ab + (long long)(m0 + row) * lda + k0 + c4);
                As[row][c4 + 0] = to_tf32(v.x);
                As[row][c4 + 1] = to_tf32(v.y);
                As[row][c4 + 2] = to_tf32(v.z);
                As[row][c4 + 3] = to_tf32(v.w);
            }
        } else {
#pragma unroll
            for (int r = 0; r < 4; r++) {
                int idx = tid + NTHREADS * r;
                int col = idx >> 5;                 // 0..31 (k within tile)
                int m4  = (idx & 31) * 4;           // 0..124
                float4 v = *(const float4*)(Ab + (long long)(k0 + col) * lda + m0 + m4);
                As[m4 + 0][col] = to_tf32(v.x);
                As[m4 + 1][col] = to_tf32(v.y);
                As[m4 + 2][col] = to_tf32(v.z);
                As[m4 + 3][col] = to_tf32(v.w);
            }
        }
        // ---- load B tile -> Bs[k][n] (tf32-rounded) ----
        if (B_ROW) {
#pragma unroll
            for (int r = 0; r < 4; r++) {
                int idx = tid + NTHREADS * r;
                int k  = idx >> 5;                  // 0..31
                int n4 = (idx & 31) * 4;            // 0..124
                float4 v = *(const float4*)(Bb + (long long)(k0 + k) * ldb + n0 + n4);
                Bs[k][n4 + 0] = to_tf32(v.x);
                Bs[k][n4 + 1] = to_tf32(v.y);
                Bs[k][n4 + 2] = to_tf32(v.z);
                Bs[k][n4 + 3] = to_tf32(v.w);
            }
        } else {
#pragma unroll
            for (int r = 0; r < 4; r++) {
                int idx = tid + NTHREADS * r;
                int n  = idx >> 3;                  // 0..127
                int k4 = (idx & 7) * 4;             // 0..28
                float4 v = *(const float4*)(Bb + (long long)(n0 + n) * ldb + k0 + k4);
                Bs[k4 + 0][n] = to_tf32(v.x);
                Bs[k4 + 1][n] = to_tf32(v.y);
                Bs[k4 + 2][n] = to_tf32(v.z);
                Bs[k4 + 3][n] = to_tf32(v.w);
            }
        }
        __syncthreads();

        // ---- compute ----
#pragma unroll
        for (int kk = 0; kk < BK; kk += 8) {
            FragA af[4];
            FragB bf[2];
#pragma unroll
            for (int i = 0; i < 4; i++)
                wmma::load_matrix_sync(af[i], &As[wm + i * 16][kk], BK + 8);
#pragma unroll
            for (int j = 0; j < 2; j++)
                wmma::load_matrix_sync(bf[j], &Bs[kk][wn + j * 16], BN + 8);
#pragma unroll
            for (int i = 0; i < 4; i++)
#pragma unroll
                for (int j = 0; j < 2; j++)
                    wmma::mma_sync(cf[i][j], af[i], bf[j], cf[i][j]);
        }
        __syncthreads();
    }

    // ---- epilogue: per-warp 16x16 staging, alpha + bias ----
    float* st = &stage[wid][0][0];
#pragma unroll
    for (int i = 0; i < 4; i++) {
#pragma unroll
        for (int j = 0; j < 2; j++) {
#pragma unroll
            for (int e = 0; e < cf[i][j].num_elements; e++)
                cf[i][j].x[e] *= alpha;
            wmma::store_matrix_sync(st, cf[i][j], 20, wmma::mem_row_major);
            __syncwarp();
            const int gm = m0 + wm + i * 16;
            const int gn = n0 + wn + j * 16;
#pragma unroll
            for (int e = 0; e < 8; e++) {
                int idx = lane + 32 * e;           // 0..255
                int r  = idx >> 4;
                int cc = idx & 15;
                float v = st[r * 20 + cc];
                if (bias) v += bias[gn + cc];
                Cb[(long long)(gm + r) * ldc + gn + cc] = v;
            }
            __syncwarp();
        }
    }
}

// Row softmax over 2048 contiguous columns; one block per row.
__global__ void __launch_bounds__(256)
softmax_rows_2048(float* __restrict__ data)
{
    const int NC = 2048;
    float* p = data + (long long)blockIdx.x * NC;
    const int tid = threadIdx.x;

    float v[8];
    float m = -3.0e38f;
#pragma unroll
    for (int i = 0; i < 8; i++) {
        v[i] = p[tid + 256 * i];
        m = fmaxf(m, v[i]);
    }

    __shared__ float red[256];
    red[tid] = m;
    __syncthreads();
#pragma unroll
    for (int s = 128; s >= 1; s >>= 1) {
        if (tid < s) red[tid] = fmaxf(red[tid], red[tid + s]);
        __syncthreads();
    }
    m = red[0];
    __syncthreads();

    float sum = 0.0f;
#pragma unroll
    for (int i = 0; i < 8; i++) {
        v[i] = __expf(v[i] - m);
        sum += v[i];
    }
    red[tid] = sum;
    __syncthreads();
#pragma unroll
    for (int s = 128; s >= 1; s >>= 1) {
        if (tid < s) red[tid] += red[tid + s];
        __syncthreads();
    }
    float inv = 1.0f / red[0];
#pragma unroll
    for (int i = 0; i < 8; i++)
        p[tid + 256 * i] = v[i] * inv;
}

extern "C" void kernel_launch(void* const* d_in, const int* in_sizes, int n_in,
                              void* d_out, int out_size)
{
    const float* KEY   = (const float*)d_in[0];
    const float* VALUE = (const float*)d_in[1];
    const float* QUERY = (const float*)d_in[2];
    const float* Wk_w  = (const float*)d_in[3];
    const float* Wk_b  = (const float*)d_in[4];
    const float* Wq_w  = (const float*)d_in[5];
    const float* Wq_b  = (const float*)d_in[6];
    const float* Wv_w  = (const float*)d_in[7];
    const float* Wv_b  = (const float*)d_in[8];
    const float* lin_w = (const float*)d_in[9];
    const float* lin_b = (const float*)d_in[10];
    float* out = (float*)d_out;

    float *pWk, *pWq, *pWv, *pDist, *pCtx;
    cudaGetSymbolAddress((void**)&pWk,  g_Wk);
    cudaGetSymbolAddress((void**)&pWq,  g_Wq);
    cudaGetSymbolAddress((void**)&pWv,  g_Wv);
    cudaGetSymbolAddress((void**)&pDist, g_dist);
    cudaGetSymbolAddress((void**)&pCtx,  g_ctx);

    dim3 blk(NTHREADS);

    // Projections: [16384,256] x [256,1024] (W stored [1024,256] -> B col)
    gemm_tf32<false, false><<<dim3(8, 128, 1), blk>>>(
        KEY,   Wk_w, pWk, Wk_b, 16384, 1024, 256, 256, 256, 1024, 0, 0, 0, 1.0f);
    gemm_tf32<false, false><<<dim3(8, 128, 1), blk>>>(
        QUERY, Wq_w, pWq, Wq_b, 16384, 1024, 256, 256, 256, 1024, 0, 0, 0, 1.0f);
    gemm_tf32<false, false><<<dim3(8, 128, 1), blk>>>(
        VALUE, Wv_w, pWv, Wv_b, 16384, 1024, 256, 256, 256, 1024, 0, 0, 0, 1.0f);

    // dist[b,i,k] = Wk[b,i,:] . Wq[b,k,:] * (1/32)   (B = Wq, col layout)
    gemm_tf32<false, false><<<dim3(16, 16, 8), blk>>>(
        pWk, pWq, pDist, nullptr, 2048, 2048, 1024, 1024, 1024, 2048,
        2048LL * 1024, 2048LL * 1024, 2048LL * 2048, 0.03125f);

    // softmax over last axis (contiguous rows)
    softmax_rows_2048<<<16384, 256>>>(pDist);

    // ctx[b,k,h] = sum_i w[b,i,k] * Wv[b,i,h]   (A = weights, col layout; B = Wv row)
    gemm_tf32<true, true><<<dim3(8, 16, 8), blk>>>(
        pDist, pWv, pCtx, nullptr, 2048, 1024, 2048, 2048, 1024, 1024,
        2048LL * 2048, 2048LL * 1024, 2048LL * 1024, 1.0f);

    // out = ctx @ lin_w.T + lin_b : [16384,1024] x [1024,256]
    gemm_tf32<false, false><<<dim3(2, 128, 1), blk>>>(
        pCtx, lin_w, out, lin_b, 16384, 256, 1024, 1024, 1024, 256,
        0, 0, 0, 1.0f);
}

// round 3
// speedup vs baseline: 3.7467x; 3.7467x over previous
#include <cuda_runtime.h>
#include <cstdint>

// ---------------------------------------------------------------------------
//   B=8, NK=NQ=2048, D=256, H=1024
//   All GEMMs NT: C[m,n] = alpha*sum_k A[m,k]*B[n,k] (+bias[n]), K-major A/B.
//   mma.sync.m16n8k8.tf32 + ldmatrix + cp.async 3-stage pipeline.
// ---------------------------------------------------------------------------

#define NSTAGE 3
#define STAGE_BYTES 32768              // A 16KB + B 16KB
#define DYN_SMEM (NSTAGE * STAGE_BYTES)

// ---- scratch (allocation forbidden -> device globals) ----
__device__ float g_rK[4194304];        // rounded KEY    [8,2048,256]
__device__ float g_rQ[4194304];
__device__ float g_rV[4194304];
__device__ float g_wk[262144];         // rounded weights [1024,256]
__device__ float g_wq[262144];
__device__ float g_wv[262144];
__device__ float g_wl[262144];         // rounded lin_w   [256,1024]
__device__ float g_Wk[16777216];       // projections [8,2048,1024]
__device__ float g_Wq[16777216];
__device__ float g_Wv[16777216];
__device__ float g_dist[33554432];     // [8,2048,2048]
__device__ float g_wT[33554432];
__device__ float g_WvT[16777216];
__device__ float g_ctx[16777216];

// ---------------------------------------------------------------------------
__device__ __forceinline__ float rna_tf32(float x) {
    float r;
    asm("cvt.rna.tf32.f32 %0, %1;" : "=f"(r) : "f"(x));
    return r;
}
__device__ __forceinline__ uint32_t smem_u32(const void* p) {
    uint32_t a;
    asm("{ .reg .u64 t; cvta.to.shared.u64 t, %1; cvt.u32.u64 %0, t; }" : "=r"(a) : "l"(p));
    return a;
}
__device__ __forceinline__ void cp16(uint32_t dst, const void* src) {
    asm volatile("cp.async.cg.shared.global [%0], [%1], 16;" :: "r"(dst), "l"(src));
}
__device__ __forceinline__ void ldm4(uint32_t& a, uint32_t& b, uint32_t& c, uint32_t& d,
                                     uint32_t addr) {
    asm volatile("ldmatrix.sync.aligned.m8n8.x4.shared.b16 {%0,%1,%2,%3}, [%4];"
                 : "=r"(a), "=r"(b), "=r"(c), "=r"(d) : "r"(addr));
}
__device__ __forceinline__ void mma8(float* d, const uint32_t* a, const uint32_t* b) {
    asm volatile(
        "mma.sync.aligned.m16n8k8.row.col.f32.tf32.tf32.f32 "
        "{%0,%1,%2,%3}, {%4,%5,%6,%7}, {%8,%9}, {%0,%1,%2,%3};"
        : "+f"(d[0]), "+f"(d[1]), "+f"(d[2]), "+f"(d[3])
        : "r"(a[0]), "r"(a[1]), "r"(a[2]), "r"(a[3]), "r"(b[0]), "r"(b[1]));
}

// ---------------------------------------------------------------------------
// C tile 128x128 per CTA. 8 warps (2m x 4n), warp tile 64x32.
// A: [M,K] row-major. B: [N,K] row-major. C: [M,ldc] row-major.
template<bool ROUND>
__global__ void __launch_bounds__(256, 2)
gemm_tf32(const float* __restrict__ A, const float* __restrict__ B,
          float* __restrict__ C, const float* __restrict__ bias,
          int K, int ldc,
          long long sA, long long sB, long long sC, float alpha)
{
    extern __shared__ char smem[];
    const int tid = threadIdx.x;
    const int lane = tid & 31;
    const int wid = tid >> 5;
    const int m0 = blockIdx.y * 128;
    const int n0 = blockIdx.x * 128;
    const int wm = (wid >> 2) * 64;    // 0 or 64
    const int wn = (wid & 3) * 32;     // 0,32,64,96

    const float* Ab = A + (long long)blockIdx.z * sA + (long long)m0 * K;
    const float* Bb = B + (long long)blockIdx.z * sB + (long long)n0 * K;
    float*       Cb = C + (long long)blockIdx.z * sC;

    const uint32_t sbase = smem_u32(smem);

    // cp.async per-thread pattern: 4 rounds per operand per stage
    const int r0row = tid >> 3;                         // 0..31
    const int seg   = tid & 7;                          // 16B segment
    const uint32_t swoff = (uint32_t)(seg * 16) ^ (uint32_t)((r0row & 7) << 4);

    // ldmatrix per-lane addressing (swizzled K-major tiles, 128B rows)
    const uint32_t xorv = (uint32_t)((lane & 7) << 4);
    const int laneA_row = ((lane >> 3) & 1) * 8 + (lane & 7);
    const uint32_t laneA_col = (uint32_t)((lane >> 4) * 16);
    const int laneB_row = (lane >> 4) * 8 + (lane & 7);
    const uint32_t laneB_col = (uint32_t)(((lane >> 3) & 1) * 16);

    float acc[4][4][4];
#pragma unroll
    for (int i = 0; i < 4; i++)
#pragma unroll
        for (int j = 0; j < 4; j++)
#pragma unroll
            for (int e = 0; e < 4; e++)
                acc[i][j][e] = 0.0f;

    const int NC = K >> 5;   // 32-wide K chunks

    // ---- prologue: stages 0,1 ----
#pragma unroll
    for (int s = 0; s < NSTAGE - 1; s++) {
        const uint32_t da = sbase + s * STAGE_BYTES;
        const uint32_t db = da + 16384;
        const int bk = s * 32;
#pragma unroll
        for (int i = 0; i < 4; i++) {
            const int row = r0row + 32 * i;
            cp16(da + (uint32_t)(row * 128) + swoff, Ab + (long long)row * K + bk + seg * 4);
            cp16(db + (uint32_t)(row * 128) + swoff, Bb + (long long)row * K + bk + seg * 4);
        }
        asm volatile("cp.async.commit_group;" ::: "memory");
    }

    // ---- main loop ----
    for (int j = 0; j < NC; j++) {
        asm volatile("cp.async.wait_group %0;" :: "n"(NSTAGE - 2) : "memory");
        __syncthreads();

        // issue stage j+2
        const int jf = j + NSTAGE - 1;
        if (jf < NC) {
            const uint32_t da = sbase + (jf % NSTAGE) * STAGE_BYTES;
            const uint32_t db = da + 16384;
            const int bk = jf * 32;
#pragma unroll
            for (int i = 0; i < 4; i++) {
                const int row = r0row + 32 * i;
                cp16(da + (uint32_t)(row * 128) + swoff, Ab + (long long)row * K + bk + seg * 4);
                cp16(db + (uint32_t)(row * 128) + swoff, Bb + (long long)row * K + bk + seg * 4);
            }
        }
        asm volatile("cp.async.commit_group;" ::: "memory");

        // compute on stage j
        const uint32_t ta = sbase + (j % NSTAGE) * STAGE_BYTES;
        const uint32_t tb = ta + 16384;
        const uint32_t baseA = ta + (uint32_t)((wm + laneA_row) * 128);
        const uint32_t baseB = tb + (uint32_t)((wn + laneB_row) * 128);

#pragma unroll
        for (int ks = 0; ks < 4; ks++) {
            const uint32_t kb = (uint32_t)(ks * 32);   // kk*4 bytes
            uint32_t af[4][4];
            uint32_t bf[2][4];
#pragma unroll
            for (int mt = 0; mt < 4; mt++)
                ldm4(af[mt][0], af[mt][1], af[mt][2], af[mt][3],
                     baseA + (uint32_t)(mt * 16 * 128) + ((kb + laneA_col) ^ xorv));
#pragma unroll
            for (int nt2 = 0; nt2 < 2; nt2++)
                ldm4(bf[nt2][0], bf[nt2][1], bf[nt2][2], bf[nt2][3],
                     baseB + (uint32_t)(nt2 * 16 * 128) + ((kb + laneB_col) ^ xorv));
#pragma unroll
            for (int mt = 0; mt < 4; mt++)
#pragma unroll
                for (int nt = 0; nt < 4; nt++)
                    mma8(acc[mt][nt], af[mt], &bf[nt >> 1][(nt & 1) * 2]);
        }
    }

    // ---- epilogue: direct float2 stores, alpha + bias (+ tf32 rounding) ----
    const int erow = lane >> 2;
    const int ecol = (lane & 3) * 2;
#pragma unroll
    for (int mt = 0; mt < 4; mt++) {
#pragma unroll
        for (int nt = 0; nt < 4; nt++) {
            const int gm = m0 + wm + mt * 16 + erow;
            const int gn = n0 + wn + nt * 8 + ecol;
            float b0 = 0.0f, b1 = 0.0f;
            if (bias) { b0 = __ldg(bias + gn); b1 = __ldg(bias + gn + 1); }
            float2 v0, v1;
            v0.x = acc[mt][nt][0] * alpha + b0;
            v0.y = acc[mt][nt][1] * alpha + b1;
            v1.x = acc[mt][nt][2] * alpha + b0;
            v1.y = acc[mt][nt][3] * alpha + b1;
            if (ROUND) {
                v0.x = rna_tf32(v0.x); v0.y = rna_tf32(v0.y);
                v1.x = rna_tf32(v1.x); v1.y = rna_tf32(v1.y);
            }
            *(float2*)(Cb + (long long)gm * ldc + gn) = v0;
            *(float2*)(Cb + (long long)(gm + 8) * ldc + gn) = v1;
        }
    }
}

// ---------------------------------------------------------------------------
// Elementwise rna->tf32 rounding copy (float4 granularity).
__global__ void __launch_bounds__(256)
roundcpy(const float4* __restrict__ in, float4* __restrict__ out, int n4)
{
    for (int i = blockIdx.x * blockDim.x + threadIdx.x; i < n4;
         i += gridDim.x * blockDim.x) {
        float4 v = in[i];
        v.x = rna_tf32(v.x); v.y = rna_tf32(v.y);
        v.z = rna_tf32(v.z); v.w = rna_tf32(v.w);
        out[i] = v;
    }
}

// ---------------------------------------------------------------------------
// Row softmax over 2048 contiguous columns; rounds output to tf32 (rna).
__global__ void __launch_bounds__(256)
softmax_rows_2048(float* __restrict__ data)
{
    float* p = data + (long long)blockIdx.x * 2048;
    const int tid = threadIdx.x;
    float v[8];
    float m = -3.0e38f;
#pragma unroll
    for (int i = 0; i < 8; i++) { v[i] = p[tid + 256 * i]; m = fmaxf(m, v[i]); }

    __shared__ float red[256];
    red[tid] = m; __syncthreads();
#pragma unroll
    for (int s = 128; s >= 1; s >>= 1) {
        if (tid < s) red[tid] = fmaxf(red[tid], red[tid + s]);
        __syncthreads();
    }
    m = red[0]; __syncthreads();

    float sum = 0.0f;
#pragma unroll
    for (int i = 0; i < 8; i++) { v[i] = __expf(v[i] - m); sum += v[i]; }
    red[tid] = sum; __syncthreads();
#pragma unroll
    for (int s = 128; s >= 1; s >>= 1) {
        if (tid < s) red[tid] += red[tid + s];
        __syncthreads();
    }
    const float inv = 1.0f / red[0];
#pragma unroll
    for (int i = 0; i < 8; i++) p[tid + 256 * i] = rna_tf32(v[i] * inv);
}

// ---------------------------------------------------------------------------
// Batched tiled transpose: in [R,Cc] -> out [Cc,R] per batch (bit-exact copy).
__global__ void __launch_bounds__(256)
transpose_b(const float* __restrict__ in, float* __restrict__ out, int R, int Cc)
{
    __shared__ float t[32][33];
    const long long bo = (long long)blockIdx.z * R * Cc;
    const float* ib = in + bo;
    float* ob = out + bo;
    const int c0 = blockIdx.x * 32, r0 = blockIdx.y * 32;
    const int lx = threadIdx.x & 31, ly = threadIdx.x >> 5;
#pragma unroll
    for (int rr = 0; rr < 32; rr += 8)
        t[ly + rr][lx] = ib[(long long)(r0 + ly + rr) * Cc + c0 + lx];
    __syncthreads();
#pragma unroll
    for (int rr = 0; rr < 32; rr += 8)
        ob[(long long)(c0 + ly + rr) * R + r0 + lx] = t[lx][ly + rr];
}

// ---------------------------------------------------------------------------
extern "C" void kernel_launch(void* const* d_in, const int* in_sizes, int n_in,
                              void* d_out, int out_size)
{
    const float* KEY   = (const float*)d_in[0];
    const float* VALUE = (const float*)d_in[1];
    const float* QUERY = (const float*)d_in[2];
    const float* Wk_w  = (const float*)d_in[3];
    const float* Wk_b  = (const float*)d_in[4];
    const float* Wq_w  = (const float*)d_in[5];
    const float* Wq_b  = (const float*)d_in[6];
    const float* Wv_w  = (const float*)d_in[7];
    const float* Wv_b  = (const float*)d_in[8];
    const float* lin_w = (const float*)d_in[9];
    const float* lin_b = (const float*)d_in[10];
    float* out = (float*)d_out;

    float *rK, *rQ, *rV, *wk, *wq, *wv, *wl;
    float *pWk, *pWq, *pWv, *pD, *pWT, *pVT, *pC;
    cudaGetSymbolAddress((void**)&rK, g_rK);
    cudaGetSymbolAddress((void**)&rQ, g_rQ);
    cudaGetSymbolAddress((void**)&rV, g_rV);
    cudaGetSymbolAddress((void**)&wk, g_wk);
    cudaGetSymbolAddress((void**)&wq, g_wq);
    cudaGetSymbolAddress((void**)&wv, g_wv);
    cudaGetSymbolAddress((void**)&wl, g_wl);
    cudaGetSymbolAddress((void**)&pWk, g_Wk);
    cudaGetSymbolAddress((void**)&pWq, g_Wq);
    cudaGetSymbolAddress((void**)&pWv, g_Wv);
    cudaGetSymbolAddress((void**)&pD,  g_dist);
    cudaGetSymbolAddress((void**)&pWT, g_wT);
    cudaGetSymbolAddress((void**)&pVT, g_WvT);
    cudaGetSymbolAddress((void**)&pC,  g_ctx);

    cudaFuncSetAttribute(gemm_tf32<true>,  cudaFuncAttributeMaxDynamicSharedMemorySize, DYN_SMEM);
    cudaFuncSetAttribute(gemm_tf32<false>, cudaFuncAttributeMaxDynamicSharedMemorySize, DYN_SMEM);

    dim3 blk(256);

    // round inputs + weights to tf32 (rna) so every MMA operand is pre-rounded
    roundcpy<<<1024, blk>>>((const float4*)KEY,   (float4*)rK, 4194304 / 4);
    roundcpy<<<1024, blk>>>((const float4*)QUERY, (float4*)rQ, 4194304 / 4);
    roundcpy<<<1024, blk>>>((const float4*)VALUE, (float4*)rV, 4194304 / 4);
    roundcpy<<<256,  blk>>>((const float4*)Wk_w,  (float4*)wk, 262144 / 4);
    roundcpy<<<256,  blk>>>((const float4*)Wq_w,  (float4*)wq, 262144 / 4);
    roundcpy<<<256,  blk>>>((const float4*)Wv_w,  (float4*)wv, 262144 / 4);
    roundcpy<<<256,  blk>>>((const float4*)lin_w, (float4*)wl, 262144 / 4);

    // projections: M=16384, N=1024, K=256 (rounded outputs feed dist/ctx GEMMs)
    gemm_tf32<true><<<dim3(8, 128, 1), blk, DYN_SMEM>>>(rK, wk, pWk, Wk_b, 256, 1024, 0, 0, 0, 1.0f);
    gemm_tf32<true><<<dim3(8, 128, 1), blk, DYN_SMEM>>>(rQ, wq, pWq, Wq_b, 256, 1024, 0, 0, 0, 1.0f);
    gemm_tf32<true><<<dim3(8, 128, 1), blk, DYN_SMEM>>>(rV, wv, pWv, Wv_b, 256, 1024, 0, 0, 0, 1.0f);

    // dist[b,i,k] = Wk.Wq/32 : M=N=2048, K=1024, batched over 8
    gemm_tf32<false><<<dim3(16, 16, 8), blk, DYN_SMEM>>>(pWk, pWq, pD, nullptr, 1024, 2048,
        2048LL * 1024, 2048LL * 1024, 2048LL * 2048, 0.03125f);

    softmax_rows_2048<<<16384, blk>>>(pD);

    // w [i,k] -> wT [k,i];  Wv [i,h] -> WvT [h,i]
    transpose_b<<<dim3(64, 64, 8), blk>>>(pD,  pWT, 2048, 2048);
    transpose_b<<<dim3(32, 64, 8), blk>>>(pWv, pVT, 2048, 1024);

    // ctx[b,k,h] = wT . WvT^T : M=2048, N=1024, K=2048, batched
    gemm_tf32<true><<<dim3(8, 16, 8), blk, DYN_SMEM>>>(pWT, pVT, pC, nullptr, 2048, 1024,
        2048LL * 2048, 2048LL * 1024, 2048LL * 1024, 1.0f);

    // out = ctx @ lin_w.T + lin_b : M=16384, N=256, K=1024
    gemm_tf32<false><<<dim3(2, 128, 1), blk, DYN_SMEM>>>(pC, wl, out, lin_b, 1024, 256, 0, 0, 0, 1.0f);
}